// round 13
// baseline (speedup 1.0000x reference)
#include <cuda_runtime.h>
#include <cuda_fp16.h>
#include <cstdint>
#include <math.h>
#include <stdlib.h>

#define NNODES 100000
#define NEDGES 1600000
#define INDIM  128
#define HIDDIM 128
#define OUTDIM 64

namespace {
struct EagerEnv { EagerEnv() { setenv("CUDA_MODULE_LOADING", "EAGER", 1); } };
EagerEnv g_eager_env;
}

// ---------------- scratch: 58.0 MB total ----------------
__device__ __half g_G  [(size_t)NNODES * HIDDIM];  // 25.6MB: pre-relu h1 fp16; [:,0:64] recycled for xw2
__device__ __half g_x16[(size_t)NNODES * INDIM];   // 25.6MB: x converted to fp16
__device__ float  g_norm[NEDGES];                  // 6.4MB: per-edge ew, then full norm
__device__ float  g_nd[NNODES];                    // 0.4MB: deg, then dis = rsqrt(deg+1)

// ---------------- x -> fp16 staging ----------------
__global__ void __launch_bounds__(256) x16_kernel(const float* __restrict__ x) {
    int t = blockIdx.x * 256 + threadIdx.x;          // NNODES*16 threads, 8 elems each
    if (t >= NNODES * 16) return;
    const float4* xp = ((const float4*)x) + (size_t)t * 2;
    float4 a = __ldg(xp), b = __ldg(xp + 1);
    __half2 h0 = __floats2half2_rn(a.x, a.y);
    __half2 h1 = __floats2half2_rn(a.z, a.w);
    __half2 h2 = __floats2half2_rn(b.x, b.y);
    __half2 h3 = __floats2half2_rn(b.z, b.w);
    uint4 v;
    v.x = *(unsigned int*)&h0; v.y = *(unsigned int*)&h1;
    v.z = *(unsigned int*)&h2; v.w = *(unsigned int*)&h3;
    ((uint4*)g_x16)[t] = v;
}

// ---------------- prologue kernels ----------------
__global__ void __launch_bounds__(256) zero_nd_kernel() {
    int i = blockIdx.x * 256 + threadIdx.x;
    if (i < NNODES) g_nd[i] = 0.0f;
}

__global__ void __launch_bounds__(256) ew_deg_kernel(
        const float* __restrict__ curv, const int* __restrict__ dst,
        const float* __restrict__ mw1, const float* __restrict__ mb1,
        const float* __restrict__ mw2, const float* __restrict__ mb2, int E) {
    int e = blockIdx.x * 256 + threadIdx.x;
    if (e >= E) return;
    float c = curv[e];
    float s = __ldg(mb2);
#pragma unroll
    for (int j = 0; j < 16; j++) {
        float h = fmaf(c, __ldg(&mw1[j]), __ldg(&mb1[j]));
        h = fmaxf(h, 0.0f);
        s = fmaf(h, __ldg(&mw2[j]), s);
    }
    float w  = 1.0f / (1.0f + __expf(-s));
    float ew = fmaf(0.9f, w, 0.1f);
    g_norm[e] = ew;
    atomicAdd(&g_nd[dst[e]], ew);
}

__global__ void __launch_bounds__(256) dis_kernel() {
    int i = blockIdx.x * 256 + threadIdx.x;
    if (i < NNODES) g_nd[i] = rsqrtf(g_nd[i] + 1.0f);
}

__global__ void __launch_bounds__(256) norm_fin_kernel(
        const int* __restrict__ src, const int* __restrict__ dst, int E) {
    int e = blockIdx.x * 256 + threadIdx.x;
    if (e >= E) return;
    g_norm[e] *= __ldg(&g_nd[src[e]]) * __ldg(&g_nd[dst[e]]);
}

// ---------------- zero the u staging buffer (d_out) ----------------
__global__ void __launch_bounds__(256) zero_out_kernel(float* __restrict__ out) {
    int t = blockIdx.x * 256 + threadIdx.x;          // NNODES*16 threads
    if (t >= NNODES * 16) return;
    ((float4*)out)[t] = make_float4(0.f, 0.f, 0.f, 0.f);
}

// ---------------- layer-1 scatter: u[dst] += norm * x16[src] (64-col half H) ----------------
__global__ void __launch_bounds__(256) uscat_kernel(
        const int* __restrict__ src, const int* __restrict__ dst,
        float* __restrict__ out, int E, int H) {
    int t = blockIdx.x * 256 + threadIdx.x;          // E*16 threads
    int e = t >> 4, lane = t & 15;
    if (e >= E) return;
    int s = __ldg(&src[e]);
    int d = __ldg(&dst[e]);
    float n = g_norm[e];
    uint2 raw = __ldg((const uint2*)(g_x16 + (size_t)s * INDIM + H * 64) + lane);
    __half2 h0 = *(__half2*)&raw.x;
    __half2 h1 = *(__half2*)&raw.y;
    float2 f0 = __half22float2(h0);
    float2 f1 = __half22float2(h1);
    float4 v = make_float4(n * f0.x, n * f0.y, n * f1.x, n * f1.y);
    float4* p = ((float4*)out) + (size_t)d * 16 + lane;
    asm volatile("red.global.add.v4.f32 [%0], {%1, %2, %3, %4};"
                 :: "l"(p), "f"(v.x), "f"(v.y), "f"(v.z), "f"(v.w) : "memory");
}

// ---------------- G accumulation: G(+)= (u + dis^2*x16_half) @ W1[64H:64H+64, :] (+b1 at H=1) ----------------
template <int H>
__global__ void __launch_bounds__(256) gacc_kernel(
        const float* __restrict__ u,        // d_out, [M,64] fp32 (scatter only)
        const float* __restrict__ W1,       // [128,128]
        const float* __restrict__ b1, int M) {
    __shared__ float sW[64 * 32];
    const int tid = threadIdx.x;
    const int col0 = blockIdx.y * 32;
    for (int i = tid; i < 64 * 32 / 4; i += 256) {
        int k = i >> 3, j4 = i & 7;
        ((float4*)sW)[i] = ((const float4*)(W1 + (size_t)(64 * H + k) * HIDDIM + col0))[j4];
    }
    __syncthreads();
    const int row = blockIdx.x * 256 + tid;
    if (row >= M) return;

    float dd = g_nd[row];
    float d2 = dd * dd;

    float acc[32];
#pragma unroll
    for (int j = 0; j < 32; j++) acc[j] = 0.0f;
    const float4* ur = (const float4*)(u + (size_t)row * 64);
    const uint2*  xr = (const uint2*)(g_x16 + (size_t)row * INDIM + H * 64);
#pragma unroll 1
    for (int k4 = 0; k4 < 16; k4++) {
        float4 uv = __ldg(&ur[k4]);
        uint2 raw = __ldg(&xr[k4]);
        float2 xf0 = __half22float2(*(__half2*)&raw.x);
        float2 xf1 = __half22float2(*(__half2*)&raw.y);
        uv.x = fmaf(d2, xf0.x, uv.x);
        uv.y = fmaf(d2, xf0.y, uv.y);
        uv.z = fmaf(d2, xf1.x, uv.z);
        uv.w = fmaf(d2, xf1.y, uv.w);
#pragma unroll
        for (int kk = 0; kk < 4; kk++) {
            float xs = (kk == 0) ? uv.x : (kk == 1) ? uv.y : (kk == 2) ? uv.z : uv.w;
            const float4* wrow = (const float4*)(sW + (k4 * 4 + kk) * 32);
#pragma unroll
            for (int j4 = 0; j4 < 8; j4++) {
                float4 w = wrow[j4];
                acc[j4*4+0] = fmaf(xs, w.x, acc[j4*4+0]);
                acc[j4*4+1] = fmaf(xs, w.y, acc[j4*4+1]);
                acc[j4*4+2] = fmaf(xs, w.z, acc[j4*4+2]);
                acc[j4*4+3] = fmaf(xs, w.w, acc[j4*4+3]);
            }
        }
    }
    __half2* gp = (__half2*)(g_G + (size_t)row * HIDDIM + col0);
#pragma unroll
    for (int j2 = 0; j2 < 16; j2++) {
        float a0 = acc[2*j2], a1 = acc[2*j2+1];
        if (H == 1) {
            float2 old = __half22float2(gp[j2]);
            a0 += old.x + __ldg(&b1[col0 + 2*j2]);
            a1 += old.y + __ldg(&b1[col0 + 2*j2 + 1]);
        }
        gp[j2] = __floats2half2_rn(a0, a1);
    }
}

// ---------------- fused layer-2 GEMM: xw2 = relu(G) @ W2 (in-place into G[:,0:64]) ----------------
__global__ void __launch_bounds__(256) fused_l2_kernel(
        const float* __restrict__ W2,       // [128,64]
        const float* __restrict__ b2,
        float* __restrict__ out, int M) {
    constexpr int RPB   = 64;
    constexpr int PITCH = 130;
    __shared__ __half sG[RPB * PITCH];      // 16640 B
    __shared__ __half sW[128 * 64];         // 16384 B

    const int tid  = threadIdx.x;
    const int row0 = blockIdx.x * RPB;

    for (int i = tid; i < RPB * 16; i += 256) {
        int r = i >> 4, q = i & 15;
        uint4 v = make_uint4(0u, 0u, 0u, 0u);
        if (row0 + r < M)
            v = __ldg((const uint4*)(g_G + (size_t)(row0 + r) * HIDDIM) + q);
        unsigned int* dp = (unsigned int*)(sG + r * PITCH) + q * 4;
        dp[0] = v.x; dp[1] = v.y; dp[2] = v.z; dp[3] = v.w;
    }
    for (int i = tid; i < 128 * 64 / 2; i += 256) {
        float2 f = __ldg(((const float2*)W2) + i);
        ((__half2*)sW)[i] = __floats2half2_rn(f.x, f.y);
    }
    __syncthreads();

    const int r   = tid >> 2;
    const int g   = tid & 3;
    const int row = row0 + r;

    float acc[16];
#pragma unroll
    for (int j = 0; j < 16; j++) acc[j] = 0.0f;

    const __half2* gRow = (const __half2*)(sG + r * PITCH);
#pragma unroll 4
    for (int k2 = 0; k2 < 64; k2++) {
        float2 gf = __half22float2(gRow[k2]);
        float g0 = fmaxf(gf.x, 0.0f);
        float g1 = fmaxf(gf.y, 0.0f);
        const __half2* w0 = (const __half2*)(sW + (2 * k2)     * 64 + g * 16);
        const __half2* w1 = (const __half2*)(sW + (2 * k2 + 1) * 64 + g * 16);
#pragma unroll
        for (int j2 = 0; j2 < 8; j2++) {
            float2 a = __half22float2(w0[j2]);
            float2 b = __half22float2(w1[j2]);
            acc[2*j2]   = fmaf(g0, a.x, fmaf(g1, b.x, acc[2*j2]));
            acc[2*j2+1] = fmaf(g0, a.y, fmaf(g1, b.y, acc[2*j2+1]));
        }
    }

    if (row >= M) return;
    float dd = g_nd[row]; float d2 = dd * dd;

    __half2* xp = (__half2*)(g_G + (size_t)row * HIDDIM + g * 16);
#pragma unroll
    for (int j2 = 0; j2 < 8; j2++)
        xp[j2] = __floats2half2_rn(acc[2*j2], acc[2*j2+1]);

    float4* op = (float4*)(out + (size_t)row * OUTDIM + g * 16);
#pragma unroll
    for (int j4 = 0; j4 < 4; j4++) {
        float4 o;
        o.x = fmaf(d2, acc[4*j4+0], __ldg(&b2[g*16 + 4*j4 + 0]));
        o.y = fmaf(d2, acc[4*j4+1], __ldg(&b2[g*16 + 4*j4 + 1]));
        o.z = fmaf(d2, acc[4*j4+2], __ldg(&b2[g*16 + 4*j4 + 2]));
        o.w = fmaf(d2, acc[4*j4+3], __ldg(&b2[g*16 + 4*j4 + 3]));
        op[j4] = o;
    }
}

// ---------------- 64-dim scatter: out[dst] += norm * xw2_fp16[src] ----------------
__global__ void __launch_bounds__(256) scatter64_kernel(
        const int* __restrict__ src, const int* __restrict__ dst,
        float* __restrict__ out, int E) {
    int t = blockIdx.x * 256 + threadIdx.x;
    int e = t >> 4, lane = t & 15;
    if (e >= E) return;
    int s = __ldg(&src[e]);
    int d = __ldg(&dst[e]);
    float n = g_norm[e];
    uint2 raw = __ldg((const uint2*)(g_G + (size_t)s * HIDDIM) + lane);
    __half2 h0 = *(__half2*)&raw.x;
    __half2 h1 = *(__half2*)&raw.y;
    float2 f0 = __half22float2(h0);
    float2 f1 = __half22float2(h1);
    float4 v = make_float4(n * f0.x, n * f0.y, n * f1.x, n * f1.y);
    float4* p = ((float4*)out) + (size_t)d * 16 + lane;
    asm volatile("red.global.add.v4.f32 [%0], {%1, %2, %3, %4};"
                 :: "l"(p), "f"(v.x), "f"(v.y), "f"(v.z), "f"(v.w) : "memory");
}

// ---------------- launch (kernel launches only) ----------------
extern "C" void kernel_launch(void* const* d_in, const int* in_sizes, int n_in,
                              void* d_out, int out_size) {
    const float* x    = (const float*)d_in[0];
    const int*   ei   = (const int*)  d_in[1];
    const float* curv = (const float*)d_in[2];
    const float* W1   = (const float*)d_in[3];
    const float* b1   = (const float*)d_in[4];
    const float* W2   = (const float*)d_in[5];
    const float* b2   = (const float*)d_in[6];
    const float* mw1  = (const float*)d_in[7];
    const float* mb1  = (const float*)d_in[8];
    const float* mw2  = (const float*)d_in[9];
    const float* mb2  = (const float*)d_in[10];
    float* out = (float*)d_out;

    const int E = in_sizes[1] / 2;
    const int M = in_sizes[0] / INDIM;
    const int* src = ei;
    const int* dst = ei + E;

    const int NB_N16 = (NNODES * 16 + 255) / 256;
    const int NB_E   = (E + 255) / 256;
    const int NB_E16 = (int)(((long long)E * 16 + 255) / 256);
    const int NB_ROW = (M + 255) / 256;

    // staging + prologue
    x16_kernel<<<NB_N16, 256>>>(x);
    zero_nd_kernel<<<(NNODES + 255) / 256, 256>>>();
    ew_deg_kernel<<<NB_E, 256>>>(curv, dst, mw1, mb1, mw2, mb2, E);
    dis_kernel<<<(NNODES + 255) / 256, 256>>>();
    norm_fin_kernel<<<NB_E, 256>>>(src, dst, E);

    // layer 1, half 0: zero u, scatter fp16 x, GEMM-accumulate (self-term folded into gacc)
    zero_out_kernel<<<NB_N16, 256>>>(out);
    uscat_kernel<<<NB_E16, 256>>>(src, dst, out, E, 0);
    gacc_kernel<0><<<dim3(NB_ROW, 4), 256>>>(out, W1, b1, M);

    // layer 1, half 1
    zero_out_kernel<<<NB_N16, 256>>>(out);
    uscat_kernel<<<NB_E16, 256>>>(src, dst, out, E, 1);
    gacc_kernel<1><<<dim3(NB_ROW, 4), 256>>>(out, W1, b1, M);

    // layer 2: GEMM-first, then 64-dim scatter
    fused_l2_kernel<<<(M + 63) / 64, 256>>>(W2, b2, out, M);
    scatter64_kernel<<<NB_E16, 256>>>(src, dst, out, E);
}

// round 14
// speedup vs baseline: 1.1364x; 1.1364x over previous
#include <cuda_runtime.h>
#include <cuda_fp16.h>
#include <cstdint>
#include <math.h>
#include <stdlib.h>

#define NNODES 100000
#define NEDGES 1600000
#define INDIM  128
#define HIDDIM 128
#define OUTDIM 64

namespace {
struct EagerEnv { EagerEnv() { setenv("CUDA_MODULE_LOADING", "EAGER", 1); } };
EagerEnv g_eager_env;
}

// ---------------- scratch: 46.0 MB total ----------------
__device__ __half g_G[(size_t)NNODES * HIDDIM];  // 25.6MB: pre-relu h1 fp16; [:,0:64] recycled for xw2
__device__ int2   g_edge[NEDGES];                // 12.8MB: CSR-ordered (src, norm-bits)
__device__ float  g_norm[NEDGES];                // 6.4MB: per-edge ew (pre-CSR)
__device__ float  g_nd[NNODES];                  // 0.4MB: deg, then dis
__device__ int    g_cnt[NNODES];                 // 0.4MB: histogram, then placement cursor
__device__ int    g_off[NNODES + 1];             // 0.4MB: CSR offsets

// ---------------- prologue ----------------
__global__ void __launch_bounds__(256) zero_nd_cnt_kernel() {
    int i = blockIdx.x * 256 + threadIdx.x;
    if (i < NNODES) { g_nd[i] = 0.0f; g_cnt[i] = 0; }
}

__global__ void __launch_bounds__(256) ew_deg_kernel(
        const float* __restrict__ curv, const int* __restrict__ dst,
        const float* __restrict__ mw1, const float* __restrict__ mb1,
        const float* __restrict__ mw2, const float* __restrict__ mb2, int E) {
    int e = blockIdx.x * 256 + threadIdx.x;
    if (e >= E) return;
    float c = curv[e];
    float s = __ldg(mb2);
#pragma unroll
    for (int j = 0; j < 16; j++) {
        float h = fmaf(c, __ldg(&mw1[j]), __ldg(&mb1[j]));
        h = fmaxf(h, 0.0f);
        s = fmaf(h, __ldg(&mw2[j]), s);
    }
    float w  = 1.0f / (1.0f + __expf(-s));
    float ew = fmaf(0.9f, w, 0.1f);
    g_norm[e] = ew;
    int d = __ldg(&dst[e]);
    atomicAdd(&g_nd[d], ew);
    atomicAdd(&g_cnt[d], 1);
}

__global__ void __launch_bounds__(256) dis_kernel() {
    int i = blockIdx.x * 256 + threadIdx.x;
    if (i < NNODES) g_nd[i] = rsqrtf(g_nd[i] + 1.0f);
}

// ---------------- single-block exclusive scan of g_cnt -> g_off; zero g_cnt ----------------
__global__ void __launch_bounds__(1024) scan_kernel() {
    __shared__ int sh[1024];
    const int t  = threadIdx.x;
    const int CH = (NNODES + 1023) / 1024;          // 98
    int beg = t * CH;
    int end = beg + CH; if (end > NNODES) end = NNODES;
    int sum = 0;
    for (int i = beg; i < end; i++) sum += g_cnt[i];
    sh[t] = sum;
    __syncthreads();
    for (int o = 1; o < 1024; o <<= 1) {
        int v = (t >= o) ? sh[t - o] : 0;
        __syncthreads();
        sh[t] += v;
        __syncthreads();
    }
    int run = sh[t] - sum;                           // exclusive prefix
    for (int i = beg; i < end; i++) {
        int c = g_cnt[i];
        g_off[i] = run;
        run += c;
        g_cnt[i] = 0;                                // reset as placement cursor
    }
    if (t == 1023) g_off[NNODES] = sh[1023];
}

// ---------------- CSR placement: (src, norm) pairs grouped by dst ----------------
__global__ void __launch_bounds__(256) reorder_kernel(
        const int* __restrict__ src, const int* __restrict__ dst, int E) {
    int e = blockIdx.x * 256 + threadIdx.x;
    if (e >= E) return;
    int d = __ldg(&dst[e]);
    int s = __ldg(&src[e]);
    float nm = g_norm[e] * __ldg(&g_nd[s]) * __ldg(&g_nd[d]);
    int pos = __ldg(&g_off[d]) + atomicAdd(&g_cnt[d], 1);
    g_edge[pos] = make_int2(s, __float_as_int(nm));
}

// ---------------- layer-1 pull: u_half[d] = dis^2*x_half[d] + sum_in norm*x_half[src] ----------------
// 16 lanes per node, each lane owns one float4 column group of the 64-col half.
template <int H>
__global__ void __launch_bounds__(256) pull1_kernel(
        const float* __restrict__ x, float* __restrict__ out, int M) {
    int t = blockIdx.x * 256 + threadIdx.x;
    int node = t >> 4, lane = t & 15;
    if (node >= M) return;
    int o0 = __ldg(&g_off[node]);
    int o1 = __ldg(&g_off[node + 1]);

    float4 acc = make_float4(0.f, 0.f, 0.f, 0.f);
    int i = o0;
    for (; i + 1 < o1; i += 2) {                      // 2-way unroll: overlap gathers
        int2 e0 = __ldg(&g_edge[i]);
        int2 e1 = __ldg(&g_edge[i + 1]);
        float n0 = __int_as_float(e0.y);
        float n1 = __int_as_float(e1.y);
        float4 v0 = __ldg((const float4*)(x + (size_t)e0.x * INDIM + H * 64) + lane);
        float4 v1 = __ldg((const float4*)(x + (size_t)e1.x * INDIM + H * 64) + lane);
        acc.x = fmaf(n0, v0.x, fmaf(n1, v1.x, acc.x));
        acc.y = fmaf(n0, v0.y, fmaf(n1, v1.y, acc.y));
        acc.z = fmaf(n0, v0.z, fmaf(n1, v1.z, acc.z));
        acc.w = fmaf(n0, v0.w, fmaf(n1, v1.w, acc.w));
    }
    if (i < o1) {
        int2 e0 = __ldg(&g_edge[i]);
        float n0 = __int_as_float(e0.y);
        float4 v0 = __ldg((const float4*)(x + (size_t)e0.x * INDIM + H * 64) + lane);
        acc.x = fmaf(n0, v0.x, acc.x);
        acc.y = fmaf(n0, v0.y, acc.y);
        acc.z = fmaf(n0, v0.z, acc.z);
        acc.w = fmaf(n0, v0.w, acc.w);
    }
    float dd = __ldg(&g_nd[node]);
    float d2 = dd * dd;
    float4 xs = __ldg((const float4*)(x + (size_t)node * INDIM + H * 64) + lane);
    acc.x = fmaf(d2, xs.x, acc.x);
    acc.y = fmaf(d2, xs.y, acc.y);
    acc.z = fmaf(d2, xs.z, acc.z);
    acc.w = fmaf(d2, xs.w, acc.w);
    ((float4*)out)[(size_t)node * 16 + lane] = acc;
}

// ---------------- G accumulation: G(+)= u_half @ W1[64H:64H+64, :] (+b1 at H=1), fp16 store ----------------
template <int H>
__global__ void __launch_bounds__(256) gacc_kernel(
        const float* __restrict__ u,        // d_out, [M,64] fp32
        const float* __restrict__ W1,       // [128,128]
        const float* __restrict__ b1, int M) {
    __shared__ float sW[64 * 32];
    const int tid = threadIdx.x;
    const int col0 = blockIdx.y * 32;
    for (int i = tid; i < 64 * 32 / 4; i += 256) {
        int k = i >> 3, j4 = i & 7;
        ((float4*)sW)[i] = ((const float4*)(W1 + (size_t)(64 * H + k) * HIDDIM + col0))[j4];
    }
    __syncthreads();
    const int row = blockIdx.x * 256 + tid;
    if (row >= M) return;

    float acc[32];
#pragma unroll
    for (int j = 0; j < 32; j++) acc[j] = 0.0f;
    const float4* ur = (const float4*)(u + (size_t)row * 64);
#pragma unroll 1
    for (int k4 = 0; k4 < 16; k4++) {
        float4 uv = __ldg(&ur[k4]);
#pragma unroll
        for (int kk = 0; kk < 4; kk++) {
            float xs = (kk == 0) ? uv.x : (kk == 1) ? uv.y : (kk == 2) ? uv.z : uv.w;
            const float4* wrow = (const float4*)(sW + (k4 * 4 + kk) * 32);
#pragma unroll
            for (int j4 = 0; j4 < 8; j4++) {
                float4 w = wrow[j4];
                acc[j4*4+0] = fmaf(xs, w.x, acc[j4*4+0]);
                acc[j4*4+1] = fmaf(xs, w.y, acc[j4*4+1]);
                acc[j4*4+2] = fmaf(xs, w.z, acc[j4*4+2]);
                acc[j4*4+3] = fmaf(xs, w.w, acc[j4*4+3]);
            }
        }
    }
    __half2* gp = (__half2*)(g_G + (size_t)row * HIDDIM + col0);
#pragma unroll
    for (int j2 = 0; j2 < 16; j2++) {
        float a0 = acc[2*j2], a1 = acc[2*j2+1];
        if (H == 1) {
            float2 old = __half22float2(gp[j2]);
            a0 += old.x + __ldg(&b1[col0 + 2*j2]);
            a1 += old.y + __ldg(&b1[col0 + 2*j2 + 1]);
        }
        gp[j2] = __floats2half2_rn(a0, a1);
    }
}

// ---------------- layer-2 GEMM: xw2 = relu(G) @ W2, fp16 in place into G[:,0:64] ----------------
__global__ void __launch_bounds__(256) fused_l2_kernel(
        const float* __restrict__ W2, int M) {
    constexpr int RPB   = 64;
    constexpr int PITCH = 130;
    __shared__ __half sG[RPB * PITCH];
    __shared__ __half sW[128 * 64];

    const int tid  = threadIdx.x;
    const int row0 = blockIdx.x * RPB;

    for (int i = tid; i < RPB * 16; i += 256) {
        int r = i >> 4, q = i & 15;
        uint4 v = make_uint4(0u, 0u, 0u, 0u);
        if (row0 + r < M)
            v = __ldg((const uint4*)(g_G + (size_t)(row0 + r) * HIDDIM) + q);
        unsigned int* dp = (unsigned int*)(sG + r * PITCH) + q * 4;
        dp[0] = v.x; dp[1] = v.y; dp[2] = v.z; dp[3] = v.w;
    }
    for (int i = tid; i < 128 * 64 / 2; i += 256) {
        float2 f = __ldg(((const float2*)W2) + i);
        ((__half2*)sW)[i] = __floats2half2_rn(f.x, f.y);
    }
    __syncthreads();

    const int r   = tid >> 2;
    const int g   = tid & 3;
    const int row = row0 + r;

    float acc[16];
#pragma unroll
    for (int j = 0; j < 16; j++) acc[j] = 0.0f;

    const __half2* gRow = (const __half2*)(sG + r * PITCH);
#pragma unroll 4
    for (int k2 = 0; k2 < 64; k2++) {
        float2 gf = __half22float2(gRow[k2]);
        float g0 = fmaxf(gf.x, 0.0f);
        float g1 = fmaxf(gf.y, 0.0f);
        const __half2* w0 = (const __half2*)(sW + (2 * k2)     * 64 + g * 16);
        const __half2* w1 = (const __half2*)(sW + (2 * k2 + 1) * 64 + g * 16);
#pragma unroll
        for (int j2 = 0; j2 < 8; j2++) {
            float2 a = __half22float2(w0[j2]);
            float2 b = __half22float2(w1[j2]);
            acc[2*j2]   = fmaf(g0, a.x, fmaf(g1, b.x, acc[2*j2]));
            acc[2*j2+1] = fmaf(g0, a.y, fmaf(g1, b.y, acc[2*j2+1]));
        }
    }

    if (row >= M) return;
    __half2* xp = (__half2*)(g_G + (size_t)row * HIDDIM + g * 16);
#pragma unroll
    for (int j2 = 0; j2 < 8; j2++)
        xp[j2] = __floats2half2_rn(acc[2*j2], acc[2*j2+1]);
}

// ---------------- layer-2 pull: out[d] = dis^2*xw2[d] + b2 + sum_in norm*xw2[src] ----------------
__global__ void __launch_bounds__(256) pull2_kernel(
        const float* __restrict__ b2, float* __restrict__ out, int M) {
    int t = blockIdx.x * 256 + threadIdx.x;
    int node = t >> 4, lane = t & 15;
    if (node >= M) return;
    int o0 = __ldg(&g_off[node]);
    int o1 = __ldg(&g_off[node + 1]);

    float4 acc = make_float4(0.f, 0.f, 0.f, 0.f);
    int i = o0;
    for (; i + 1 < o1; i += 2) {
        int2 e0 = __ldg(&g_edge[i]);
        int2 e1 = __ldg(&g_edge[i + 1]);
        float n0 = __int_as_float(e0.y);
        float n1 = __int_as_float(e1.y);
        uint2 r0 = __ldg((const uint2*)(g_G + (size_t)e0.x * HIDDIM) + lane);
        uint2 r1 = __ldg((const uint2*)(g_G + (size_t)e1.x * HIDDIM) + lane);
        float2 a0 = __half22float2(*(__half2*)&r0.x);
        float2 a1 = __half22float2(*(__half2*)&r0.y);
        float2 c0 = __half22float2(*(__half2*)&r1.x);
        float2 c1 = __half22float2(*(__half2*)&r1.y);
        acc.x = fmaf(n0, a0.x, fmaf(n1, c0.x, acc.x));
        acc.y = fmaf(n0, a0.y, fmaf(n1, c0.y, acc.y));
        acc.z = fmaf(n0, a1.x, fmaf(n1, c1.x, acc.z));
        acc.w = fmaf(n0, a1.y, fmaf(n1, c1.y, acc.w));
    }
    if (i < o1) {
        int2 e0 = __ldg(&g_edge[i]);
        float n0 = __int_as_float(e0.y);
        uint2 r0 = __ldg((const uint2*)(g_G + (size_t)e0.x * HIDDIM) + lane);
        float2 a0 = __half22float2(*(__half2*)&r0.x);
        float2 a1 = __half22float2(*(__half2*)&r0.y);
        acc.x = fmaf(n0, a0.x, acc.x);
        acc.y = fmaf(n0, a0.y, acc.y);
        acc.z = fmaf(n0, a1.x, acc.z);
        acc.w = fmaf(n0, a1.y, acc.w);
    }
    float dd = __ldg(&g_nd[node]);
    float d2 = dd * dd;
    uint2 rs = __ldg((const uint2*)(g_G + (size_t)node * HIDDIM) + lane);
    float2 s0 = __half22float2(*(__half2*)&rs.x);
    float2 s1 = __half22float2(*(__half2*)&rs.y);
    float4 bb = __ldg(((const float4*)b2) + lane);
    acc.x = fmaf(d2, s0.x, acc.x) + bb.x;
    acc.y = fmaf(d2, s0.y, acc.y) + bb.y;
    acc.z = fmaf(d2, s1.x, acc.z) + bb.z;
    acc.w = fmaf(d2, s1.y, acc.w) + bb.w;
    ((float4*)out)[(size_t)node * 16 + lane] = acc;
}

// ---------------- launch (kernel launches only) ----------------
extern "C" void kernel_launch(void* const* d_in, const int* in_sizes, int n_in,
                              void* d_out, int out_size) {
    const float* x    = (const float*)d_in[0];
    const int*   ei   = (const int*)  d_in[1];
    const float* curv = (const float*)d_in[2];
    const float* W1   = (const float*)d_in[3];
    const float* b1   = (const float*)d_in[4];
    const float* W2   = (const float*)d_in[5];
    const float* b2   = (const float*)d_in[6];
    const float* mw1  = (const float*)d_in[7];
    const float* mb1  = (const float*)d_in[8];
    const float* mw2  = (const float*)d_in[9];
    const float* mb2  = (const float*)d_in[10];
    float* out = (float*)d_out;

    const int E = in_sizes[1] / 2;
    const int M = in_sizes[0] / INDIM;
    const int* src = ei;
    const int* dst = ei + E;

    const int NB_N   = (NNODES + 255) / 256;
    const int NB_E   = (E + 255) / 256;
    const int NB_P   = (NNODES * 16 + 255) / 256;   // pull grids (16 lanes/node)
    const int NB_ROW = (M + 255) / 256;

    // prologue + CSR build
    zero_nd_cnt_kernel<<<NB_N, 256>>>();
    ew_deg_kernel<<<NB_E, 256>>>(curv, dst, mw1, mb1, mw2, mb2, E);
    dis_kernel<<<NB_N, 256>>>();
    scan_kernel<<<1, 1024>>>();
    reorder_kernel<<<NB_E, 256>>>(src, dst, E);

    // layer 1 by halves: pull (atomic-free) -> GEMM-accumulate
    pull1_kernel<0><<<NB_P, 256>>>(x, out, M);
    gacc_kernel<0><<<dim3(NB_ROW, 4), 256>>>(out, W1, b1, M);
    pull1_kernel<1><<<NB_P, 256>>>(x, out, M);
    gacc_kernel<1><<<dim3(NB_ROW, 4), 256>>>(out, W1, b1, M);

    // layer 2: GEMM-first, then pull directly into d_out
    fused_l2_kernel<<<(M + 63) / 64, 256>>>(W2, M);
    pull2_kernel<<<NB_P, 256>>>(b2, out, M);
}

// round 15
// speedup vs baseline: 1.4893x; 1.3106x over previous
#include <cuda_runtime.h>
#include <cuda_fp16.h>
#include <cstdint>
#include <math.h>
#include <stdlib.h>

#define NNODES 100000
#define NEDGES 1600000
#define INDIM  128
#define HIDDIM 128
#define OUTDIM 64

namespace {
struct EagerEnv { EagerEnv() { setenv("CUDA_MODULE_LOADING", "EAGER", 1); } };
EagerEnv g_eager_env;
}

// ---------------- scratch: 46.0 MB total ----------------
__device__ __half g_G[(size_t)NNODES * HIDDIM];  // 25.6MB: pre-relu h1 fp16; [:,0:64] recycled for xw2
__device__ int2   g_edge[NEDGES];                // 12.8MB: CSR-ordered (src, norm-bits)
__device__ float  g_norm[NEDGES];                // 6.4MB: per-edge ew (pre-CSR)
__device__ float  g_nd[NNODES];                  // 0.4MB: deg, then dis
__device__ int    g_cnt[NNODES];                 // 0.4MB: histogram, then placement cursor
__device__ int    g_off[NNODES + 1];             // 0.4MB: CSR offsets
__device__ int    g_bsum[512];                   // block sums for the scan

// ---------------- prologue ----------------
__global__ void __launch_bounds__(256) zero_nd_cnt_kernel() {
    int i = blockIdx.x * 256 + threadIdx.x;
    if (i < NNODES) { g_nd[i] = 0.0f; g_cnt[i] = 0; }
}

__global__ void __launch_bounds__(256) ew_deg_kernel(
        const float* __restrict__ curv, const int* __restrict__ dst,
        const float* __restrict__ mw1, const float* __restrict__ mb1,
        const float* __restrict__ mw2, const float* __restrict__ mb2, int E) {
    int e = blockIdx.x * 256 + threadIdx.x;
    if (e >= E) return;
    float c = curv[e];
    float s = __ldg(mb2);
#pragma unroll
    for (int j = 0; j < 16; j++) {
        float h = fmaf(c, __ldg(&mw1[j]), __ldg(&mb1[j]));
        h = fmaxf(h, 0.0f);
        s = fmaf(h, __ldg(&mw2[j]), s);
    }
    float w  = 1.0f / (1.0f + __expf(-s));
    float ew = fmaf(0.9f, w, 0.1f);
    g_norm[e] = ew;
    int d = __ldg(&dst[e]);
    atomicAdd(&g_nd[d], ew);
    atomicAdd(&g_cnt[d], 1);
}

__global__ void __launch_bounds__(256) dis_kernel() {
    int i = blockIdx.x * 256 + threadIdx.x;
    if (i < NNODES) g_nd[i] = rsqrtf(g_nd[i] + 1.0f);
}

// ---------------- multi-block exclusive scan: g_cnt -> g_off ----------------
// scan1: per-block smem scan; g_off[i] = exclusive-in-block prefix; g_bsum[b] = block total
__global__ void __launch_bounds__(256) scan1_kernel() {
    __shared__ int sh[256];
    int tid = threadIdx.x;
    int i = blockIdx.x * 256 + tid;
    int v = (i < NNODES) ? g_cnt[i] : 0;
    sh[tid] = v;
    __syncthreads();
#pragma unroll
    for (int o = 1; o < 256; o <<= 1) {
        int p = (tid >= o) ? sh[tid - o] : 0;
        __syncthreads();
        sh[tid] += p;
        __syncthreads();
    }
    if (i < NNODES) g_off[i] = sh[tid] - v;          // exclusive within block
    if (tid == 255) g_bsum[blockIdx.x] = sh[255];
}

// scan2: single block, exclusive scan of block totals (NB <= 512)
__global__ void __launch_bounds__(512) scan2_kernel(int nb) {
    __shared__ int sh[512];
    int tid = threadIdx.x;
    int v = (tid < nb) ? g_bsum[tid] : 0;
    sh[tid] = v;
    __syncthreads();
#pragma unroll
    for (int o = 1; o < 512; o <<= 1) {
        int p = (tid >= o) ? sh[tid - o] : 0;
        __syncthreads();
        sh[tid] += p;
        __syncthreads();
    }
    if (tid < nb) g_bsum[tid] = sh[tid] - v;         // exclusive block offset
}

// scan3: add block offsets; zero g_cnt (placement cursor); set g_off[N]=E
__global__ void __launch_bounds__(256) scan3_kernel(int E) {
    int i = blockIdx.x * 256 + threadIdx.x;
    if (i < NNODES) {
        g_off[i] += g_bsum[blockIdx.x];
        g_cnt[i] = 0;
    }
    if (i == 0) g_off[NNODES] = E;
}

// ---------------- CSR placement: (src, norm) pairs grouped by dst ----------------
__global__ void __launch_bounds__(256) reorder_kernel(
        const int* __restrict__ src, const int* __restrict__ dst, int E) {
    int e = blockIdx.x * 256 + threadIdx.x;
    if (e >= E) return;
    int d = __ldg(&dst[e]);
    int s = __ldg(&src[e]);
    float nm = g_norm[e] * __ldg(&g_nd[s]) * __ldg(&g_nd[d]);
    int pos = __ldg(&g_off[d]) + atomicAdd(&g_cnt[d], 1);
    g_edge[pos] = make_int2(s, __float_as_int(nm));
}

// ---------------- layer-1 pull: u_half[d] = dis^2*x_half[d] + sum_in norm*x_half[src] ----------------
template <int H>
__global__ void __launch_bounds__(256) pull1_kernel(
        const float* __restrict__ x, float* __restrict__ out, int M) {
    int t = blockIdx.x * 256 + threadIdx.x;
    int node = t >> 4, lane = t & 15;
    if (node >= M) return;
    int o0 = __ldg(&g_off[node]);
    int o1 = __ldg(&g_off[node + 1]);

    float4 acc = make_float4(0.f, 0.f, 0.f, 0.f);
    int i = o0;
    for (; i + 1 < o1; i += 2) {
        int2 e0 = __ldg(&g_edge[i]);
        int2 e1 = __ldg(&g_edge[i + 1]);
        float n0 = __int_as_float(e0.y);
        float n1 = __int_as_float(e1.y);
        float4 v0 = __ldg((const float4*)(x + (size_t)e0.x * INDIM + H * 64) + lane);
        float4 v1 = __ldg((const float4*)(x + (size_t)e1.x * INDIM + H * 64) + lane);
        acc.x = fmaf(n0, v0.x, fmaf(n1, v1.x, acc.x));
        acc.y = fmaf(n0, v0.y, fmaf(n1, v1.y, acc.y));
        acc.z = fmaf(n0, v0.z, fmaf(n1, v1.z, acc.z));
        acc.w = fmaf(n0, v0.w, fmaf(n1, v1.w, acc.w));
    }
    if (i < o1) {
        int2 e0 = __ldg(&g_edge[i]);
        float n0 = __int_as_float(e0.y);
        float4 v0 = __ldg((const float4*)(x + (size_t)e0.x * INDIM + H * 64) + lane);
        acc.x = fmaf(n0, v0.x, acc.x);
        acc.y = fmaf(n0, v0.y, acc.y);
        acc.z = fmaf(n0, v0.z, acc.z);
        acc.w = fmaf(n0, v0.w, acc.w);
    }
    float dd = __ldg(&g_nd[node]);
    float d2 = dd * dd;
    float4 xs = __ldg((const float4*)(x + (size_t)node * INDIM + H * 64) + lane);
    acc.x = fmaf(d2, xs.x, acc.x);
    acc.y = fmaf(d2, xs.y, acc.y);
    acc.z = fmaf(d2, xs.z, acc.z);
    acc.w = fmaf(d2, xs.w, acc.w);
    ((float4*)out)[(size_t)node * 16 + lane] = acc;
}

// ---------------- G accumulation: G(+)= u_half @ W1[64H:64H+64, :] (+b1 at H=1), fp16 store ----------------
template <int H>
__global__ void __launch_bounds__(256) gacc_kernel(
        const float* __restrict__ u,        // d_out, [M,64] fp32
        const float* __restrict__ W1,       // [128,128]
        const float* __restrict__ b1, int M) {
    __shared__ float sW[64 * 32];
    const int tid = threadIdx.x;
    const int col0 = blockIdx.y * 32;
    for (int i = tid; i < 64 * 32 / 4; i += 256) {
        int k = i >> 3, j4 = i & 7;
        ((float4*)sW)[i] = ((const float4*)(W1 + (size_t)(64 * H + k) * HIDDIM + col0))[j4];
    }
    __syncthreads();
    const int row = blockIdx.x * 256 + tid;
    if (row >= M) return;

    float acc[32];
#pragma unroll
    for (int j = 0; j < 32; j++) acc[j] = 0.0f;
    const float4* ur = (const float4*)(u + (size_t)row * 64);
#pragma unroll 1
    for (int k4 = 0; k4 < 16; k4++) {
        float4 uv = __ldg(&ur[k4]);
#pragma unroll
        for (int kk = 0; kk < 4; kk++) {
            float xs = (kk == 0) ? uv.x : (kk == 1) ? uv.y : (kk == 2) ? uv.z : uv.w;
            const float4* wrow = (const float4*)(sW + (k4 * 4 + kk) * 32);
#pragma unroll
            for (int j4 = 0; j4 < 8; j4++) {
                float4 w = wrow[j4];
                acc[j4*4+0] = fmaf(xs, w.x, acc[j4*4+0]);
                acc[j4*4+1] = fmaf(xs, w.y, acc[j4*4+1]);
                acc[j4*4+2] = fmaf(xs, w.z, acc[j4*4+2]);
                acc[j4*4+3] = fmaf(xs, w.w, acc[j4*4+3]);
            }
        }
    }
    __half2* gp = (__half2*)(g_G + (size_t)row * HIDDIM + col0);
#pragma unroll
    for (int j2 = 0; j2 < 16; j2++) {
        float a0 = acc[2*j2], a1 = acc[2*j2+1];
        if (H == 1) {
            float2 old = __half22float2(gp[j2]);
            a0 += old.x + __ldg(&b1[col0 + 2*j2]);
            a1 += old.y + __ldg(&b1[col0 + 2*j2 + 1]);
        }
        gp[j2] = __floats2half2_rn(a0, a1);
    }
}

// ---------------- layer-2 GEMM: xw2 = relu(G) @ W2, fp16 in place into G[:,0:64] ----------------
__global__ void __launch_bounds__(256) fused_l2_kernel(
        const float* __restrict__ W2, int M) {
    constexpr int RPB   = 64;
    constexpr int PITCH = 130;
    __shared__ __half sG[RPB * PITCH];
    __shared__ __half sW[128 * 64];

    const int tid  = threadIdx.x;
    const int row0 = blockIdx.x * RPB;

    for (int i = tid; i < RPB * 16; i += 256) {
        int r = i >> 4, q = i & 15;
        uint4 v = make_uint4(0u, 0u, 0u, 0u);
        if (row0 + r < M)
            v = __ldg((const uint4*)(g_G + (size_t)(row0 + r) * HIDDIM) + q);
        unsigned int* dp = (unsigned int*)(sG + r * PITCH) + q * 4;
        dp[0] = v.x; dp[1] = v.y; dp[2] = v.z; dp[3] = v.w;
    }
    for (int i = tid; i < 128 * 64 / 2; i += 256) {
        float2 f = __ldg(((const float2*)W2) + i);
        ((__half2*)sW)[i] = __floats2half2_rn(f.x, f.y);
    }
    __syncthreads();

    const int r   = tid >> 2;
    const int g   = tid & 3;
    const int row = row0 + r;

    float acc[16];
#pragma unroll
    for (int j = 0; j < 16; j++) acc[j] = 0.0f;

    const __half2* gRow = (const __half2*)(sG + r * PITCH);
#pragma unroll 4
    for (int k2 = 0; k2 < 64; k2++) {
        float2 gf = __half22float2(gRow[k2]);
        float g0 = fmaxf(gf.x, 0.0f);
        float g1 = fmaxf(gf.y, 0.0f);
        const __half2* w0 = (const __half2*)(sW + (2 * k2)     * 64 + g * 16);
        const __half2* w1 = (const __half2*)(sW + (2 * k2 + 1) * 64 + g * 16);
#pragma unroll
        for (int j2 = 0; j2 < 8; j2++) {
            float2 a = __half22float2(w0[j2]);
            float2 b = __half22float2(w1[j2]);
            acc[2*j2]   = fmaf(g0, a.x, fmaf(g1, b.x, acc[2*j2]));
            acc[2*j2+1] = fmaf(g0, a.y, fmaf(g1, b.y, acc[2*j2+1]));
        }
    }

    if (row >= M) return;
    __half2* xp = (__half2*)(g_G + (size_t)row * HIDDIM + g * 16);
#pragma unroll
    for (int j2 = 0; j2 < 8; j2++)
        xp[j2] = __floats2half2_rn(acc[2*j2], acc[2*j2+1]);
}

// ---------------- layer-2 pull: out[d] = dis^2*xw2[d] + b2 + sum_in norm*xw2[src] ----------------
__global__ void __launch_bounds__(256) pull2_kernel(
        const float* __restrict__ b2, float* __restrict__ out, int M) {
    int t = blockIdx.x * 256 + threadIdx.x;
    int node = t >> 4, lane = t & 15;
    if (node >= M) return;
    int o0 = __ldg(&g_off[node]);
    int o1 = __ldg(&g_off[node + 1]);

    float4 acc = make_float4(0.f, 0.f, 0.f, 0.f);
    int i = o0;
    for (; i + 1 < o1; i += 2) {
        int2 e0 = __ldg(&g_edge[i]);
        int2 e1 = __ldg(&g_edge[i + 1]);
        float n0 = __int_as_float(e0.y);
        float n1 = __int_as_float(e1.y);
        uint2 r0 = __ldg((const uint2*)(g_G + (size_t)e0.x * HIDDIM) + lane);
        uint2 r1 = __ldg((const uint2*)(g_G + (size_t)e1.x * HIDDIM) + lane);
        float2 a0 = __half22float2(*(__half2*)&r0.x);
        float2 a1 = __half22float2(*(__half2*)&r0.y);
        float2 c0 = __half22float2(*(__half2*)&r1.x);
        float2 c1 = __half22float2(*(__half2*)&r1.y);
        acc.x = fmaf(n0, a0.x, fmaf(n1, c0.x, acc.x));
        acc.y = fmaf(n0, a0.y, fmaf(n1, c0.y, acc.y));
        acc.z = fmaf(n0, a1.x, fmaf(n1, c1.x, acc.z));
        acc.w = fmaf(n0, a1.y, fmaf(n1, c1.y, acc.w));
    }
    if (i < o1) {
        int2 e0 = __ldg(&g_edge[i]);
        float n0 = __int_as_float(e0.y);
        uint2 r0 = __ldg((const uint2*)(g_G + (size_t)e0.x * HIDDIM) + lane);
        float2 a0 = __half22float2(*(__half2*)&r0.x);
        float2 a1 = __half22float2(*(__half2*)&r0.y);
        acc.x = fmaf(n0, a0.x, acc.x);
        acc.y = fmaf(n0, a0.y, acc.y);
        acc.z = fmaf(n0, a1.x, acc.z);
        acc.w = fmaf(n0, a1.y, acc.w);
    }
    float dd = __ldg(&g_nd[node]);
    float d2 = dd * dd;
    uint2 rs = __ldg((const uint2*)(g_G + (size_t)node * HIDDIM) + lane);
    float2 s0 = __half22float2(*(__half2*)&rs.x);
    float2 s1 = __half22float2(*(__half2*)&rs.y);
    float4 bb = __ldg(((const float4*)b2) + lane);
    acc.x = fmaf(d2, s0.x, acc.x) + bb.x;
    acc.y = fmaf(d2, s0.y, acc.y) + bb.y;
    acc.z = fmaf(d2, s1.x, acc.z) + bb.z;
    acc.w = fmaf(d2, s1.y, acc.w) + bb.w;
    ((float4*)out)[(size_t)node * 16 + lane] = acc;
}

// ---------------- launch (kernel launches only) ----------------
extern "C" void kernel_launch(void* const* d_in, const int* in_sizes, int n_in,
                              void* d_out, int out_size) {
    const float* x    = (const float*)d_in[0];
    const int*   ei   = (const int*)  d_in[1];
    const float* curv = (const float*)d_in[2];
    const float* W1   = (const float*)d_in[3];
    const float* b1   = (const float*)d_in[4];
    const float* W2   = (const float*)d_in[5];
    const float* b2   = (const float*)d_in[6];
    const float* mw1  = (const float*)d_in[7];
    const float* mb1  = (const float*)d_in[8];
    const float* mw2  = (const float*)d_in[9];
    const float* mb2  = (const float*)d_in[10];
    float* out = (float*)d_out;

    const int E = in_sizes[1] / 2;
    const int M = in_sizes[0] / INDIM;
    const int* src = ei;
    const int* dst = ei + E;

    const int NB_N   = (NNODES + 255) / 256;        // 391
    const int NB_E   = (E + 255) / 256;
    const int NB_P   = (NNODES * 16 + 255) / 256;
    const int NB_ROW = (M + 255) / 256;

    // prologue + CSR build (multi-block scan)
    zero_nd_cnt_kernel<<<NB_N, 256>>>();
    ew_deg_kernel<<<NB_E, 256>>>(curv, dst, mw1, mb1, mw2, mb2, E);
    dis_kernel<<<NB_N, 256>>>();
    scan1_kernel<<<NB_N, 256>>>();
    scan2_kernel<<<1, 512>>>(NB_N);
    scan3_kernel<<<NB_N, 256>>>(E);
    reorder_kernel<<<NB_E, 256>>>(src, dst, E);

    // layer 1 by halves: pull (atomic-free) -> GEMM-accumulate
    pull1_kernel<0><<<NB_P, 256>>>(x, out, M);
    gacc_kernel<0><<<dim3(NB_ROW, 4), 256>>>(out, W1, b1, M);
    pull1_kernel<1><<<NB_P, 256>>>(x, out, M);
    gacc_kernel<1><<<dim3(NB_ROW, 4), 256>>>(out, W1, b1, M);

    // layer 2: GEMM-first, then pull directly into d_out
    fused_l2_kernel<<<(M + 63) / 64, 256>>>(W2, M);
    pull2_kernel<<<NB_P, 256>>>(b2, out, M);
}